// round 10
// baseline (speedup 1.0000x reference)
#include <cuda_runtime.h>
#include <cstdint>

// FSMN depthwise strided FIR on GB300 — R10.
// Pipe-balancing: R9 saturated the smem crossbar (window+taps both LDS);
// R5 saturated latency at 4 warps/SMSP with a 128-reg cap. R10 splits:
//   window x-loads  -> smem  (crossbar ~1320 cyc/block-tile)
//   filter taps     -> LDG depth-4 pipe, L1-resident slab (LSU ~1900 cyc)
//   FMA             -> 1968 cyc/block-tile  == binding pipe
// plus double-buffered cp.async tile fill (R9 serialized it).
// 384 thr = 32 dpl x 2 par x 6 g; TT=96, ROWS=176; smem 2x45KB; 2 blocks/SM.
//
// out[b,t,d] = sum_{i=0..19} filt[i,d]*x[b,t-(20-i)*2,d]
//            + filt[20,d]*x[b,t,d]
//            + sum_{j=0..19} filt[21+j,d]*x[b,t+1+2j,d],  zero-padded.

#define B_   32
#define T_   2000
#define DPAL 256        // d-pairs across all of D
#define DPB  32         // d-pairs per block
#define RT   8          // outputs per thread (one parity)
#define TT   96         // t-outputs per tile (6 groups x 16)
#define TPB  7          // tiles per block; grid.x=3 -> 21 tiles (2016 >= 2000)
#define ROWS (TT + 80)  // 176 smem rows per tile
#define XWORDS (ROWS * DPB)            // 5632 u64 per buffer
#define XBYTES (XWORDS * 8)            // 45056 B
#define SMEM_BYTES (2 * XBYTES)        // 90112 B
#define CHUNKS (ROWS * 16)             // 2816 16B units per tile

__device__ __forceinline__ uint64_t f2fma(uint64_t a, uint64_t b, uint64_t c) {
    uint64_t r;
    asm("fma.rn.f32x2 %0, %1, %2, %3;" : "=l"(r) : "l"(a), "l"(b), "l"(c));
    return r;
}

__device__ __forceinline__ uint32_t smem_u32(const void* p) {
    uint32_t a;
    asm("{ .reg .u64 t; cvta.to.shared.u64 t, %1; cvt.u32.u64 %0, t; }"
        : "=r"(a) : "l"(p));
    return a;
}

// One dense stream: NT taps over smem rows rb+2l (l=0..NT+6); taps from
// GLOBAL (L1-resident) at ftb[c*DPAL] via depth-4 prefetch pipe.
// Window: 8-deep rotating ring (R5-proven shape).
template<int NT>
__device__ __forceinline__ void stream_acc(uint64_t* __restrict__ acc,
                                           const uint64_t* __restrict__ sxp,
                                           int rb,
                                           const uint64_t* __restrict__ ftb)
{
    uint64_t tp[4];
#pragma unroll
    for (int k = 0; k < 4; ++k) tp[k] = ftb[(size_t)k * DPAL];

    uint64_t w[RT];
#pragma unroll
    for (int u = 0; u < RT; ++u)
        w[u] = sxp[(rb + 2 * u) * DPB];

#pragma unroll
    for (int c = 0; c < NT; ++c) {
        const uint64_t tap = tp[c & 3];
        if (c + 4 < NT) tp[c & 3] = ftb[(size_t)(c + 4) * DPAL];
#pragma unroll
        for (int r = 0; r < RT; ++r)
            acc[r] = f2fma(tap, w[(c + r) & (RT - 1)], acc[r]);
        if (c + RT <= NT + 6)
            w[c & (RT - 1)] = sxp[(rb + 2 * (c + RT)) * DPB];
    }
}

__global__ __launch_bounds__(384, 2)
void fsmn_kernel(const float* __restrict__ x,
                 const float* __restrict__ filt,
                 float* __restrict__ out)
{
    extern __shared__ uint64_t sx[];   // [2][ROWS][DPB]

    const int tid = threadIdx.x;
    const int q0  = blockIdx.x * TPB;         // first tile index
    const int dpg = blockIdx.y * DPB;         // d-pair base
    const int b   = blockIdx.z;

    const uint64_t* __restrict__ xg =
        reinterpret_cast<const uint64_t*>(x) + (size_t)b * T_ * DPAL + dpg;
    uint64_t* __restrict__ og =
        reinterpret_cast<uint64_t*>(out) + (size_t)b * T_ * DPAL + dpg;

    const uint32_t sbase = smem_u32(sx);

    // ---- cp.async tile prefetch: 2816 16B units over 384 threads ----
    auto prefetch = [&](int buf, int qt) {
        const int tb = qt * TT;
        const uint32_t db = sbase + (uint32_t)buf * XBYTES;
#pragma unroll
        for (int k = 0; k < 8; ++k) {
            const int u = tid + k * 384;
            if (u < CHUNKS) {
                const int row = u >> 4;
                const int c16 = u & 15;
                const int t   = tb - 40 + row;
                const char* gp =
                    reinterpret_cast<const char*>(xg + (size_t)t * DPAL)
                    + c16 * 16;
                const uint32_t dst = db + (uint32_t)(row * DPB) * 8 + c16 * 16;
                const int ok = (t >= 0 && t < T_) ? 16 : 0;
                asm volatile("cp.async.cg.shared.global [%0], [%1], 16, %2;"
                             :: "r"(dst), "l"(gp), "r"(ok) : "memory");
            }
        }
        asm volatile("cp.async.commit_group;" ::: "memory");
    };

    const int dpl = tid & (DPB - 1);          // 0..31
    const int par = (tid >> 5) & 1;           // parity owned by this thread
    const int g   = tid >> 6;                 // 0..5 (16 t each)
    const uint64_t* __restrict__ fdp =
        reinterpret_cast<const uint64_t*>(filt) + dpg + dpl;

    prefetch(0, q0);

#pragma unroll
    for (int i = 0; i < TPB; ++i) {
        if (i < TPB - 1) {
            prefetch((i + 1) & 1, q0 + i + 1);
            asm volatile("cp.async.wait_group 1;" ::: "memory");
        } else {
            asm volatile("cp.async.wait_group 0;" ::: "memory");
        }
        __syncthreads();

        const int tb = (q0 + i) * TT;
        const uint64_t* __restrict__ sxp = sx + (i & 1) * XWORDS + dpl;
        const int rb = g * 16 + par;           // smem row of x[t0-40]

        uint64_t acc[RT];
#pragma unroll
        for (int r = 0; r < RT; ++r) acc[r] = 0ull;

        // A stream: left+center taps filt[0..20] over x[t0-40+2l]
        stream_acc<21>(acc, sxp, rb, fdp);
        // B stream: right taps filt[21..40] over x[t0+1+2l]
        stream_acc<20>(acc, sxp, rb + 41, fdp + (size_t)21 * DPAL);

        // ---- store 8 outputs (guard: tiles 20.. reach t >= 2000) ----
        const int t0 = tb + g * 16 + par;
#pragma unroll
        for (int r = 0; r < RT; ++r) {
            const int t = t0 + 2 * r;
            if (t < T_) og[(size_t)t * DPAL + dpl] = acc[r];
        }
        __syncthreads();   // protect buf[i&1] before next prefetch
    }
}

extern "C" void kernel_launch(void* const* d_in, const int* in_sizes, int n_in,
                              void* d_out, int out_size)
{
    const float* x    = (const float*)d_in[0];   // [32, 2000, 512] f32
    const float* filt = (const float*)d_in[1];   // [41, 512] f32
    float* out        = (float*)d_out;           // [32, 2000, 512] f32

    cudaFuncSetAttribute(fsmn_kernel,
                         cudaFuncAttributeMaxDynamicSharedMemorySize,
                         SMEM_BYTES);

    dim3 grid(3,            // 3 groups x TPB=7 tiles -> 21 t-tiles
              DPAL / DPB,   // 8 d-pair slabs
              B_);          // 32 batch
    fsmn_kernel<<<grid, 384, SMEM_BYTES>>>(x, filt, out);
}

// round 11
// speedup vs baseline: 1.3210x; 1.3210x over previous
#include <cuda_runtime.h>
#include <cstdint>

// FSMN depthwise strided FIR on GB300 — R11.
// Diagnosis across R5..R10: with 2x106KB smem blocks, L1D shrinks to ~15KB,
// so per-tile filter-tap loads were ~250-cyc L2 hits (the hidden stall that
// capped fma at 48.5%). Fix: stage the block's 10.5KB filter slab into SMEM
// once, and per phase batch-load taps smem->regs (29 cyc). Compute keeps the
// R4/R5-proven A/B-phase + rotating-window shape; fill keeps R5's
// double-buffered cp.async. Sized to fit 2 blocks/SM: TT=112, 224 threads,
// ROWS=192 -> 108.8KB smem/block (217.6KB/SM <= 228).
//
// out[b,t,d] = sum_{i=0..19} filt[i,d]*x[b,t-(20-i)*2,d]
//            + filt[20,d]*x[b,t,d]
//            + sum_{j=0..19} filt[21+j,d]*x[b,t+1+2j,d],  zero-padded.

#define B_   32
#define T_   2000
#define DPAL 256        // d-pairs across all of D
#define DPB  32         // d-pairs per block
#define RT   8          // outputs per parity chunk
#define NTH  224        // threads = 32 dp x 7 t-groups
#define TT   112        // t-outputs per tile (7 groups x 16)
#define TPB  6          // tiles per block; grid.x=3 -> 18 tiles (2016>=2000)
#define ROWS (TT + 80)  // 192 smem rows per tile
#define XWORDS (ROWS * DPB)            // 6144 u64 per buffer
#define XBYTES (XWORDS * 8)            // 49152 B
#define FWORDS (41 * DPB)              // 1312 u64
#define SMEM_BYTES (2 * XBYTES + FWORDS * 8)   // 108800 B
#define CHUNKS (ROWS * 16)             // 3072 16B units per tile

__device__ __forceinline__ uint64_t f2fma(uint64_t a, uint64_t b, uint64_t c) {
    uint64_t r;
    asm("fma.rn.f32x2 %0, %1, %2, %3;" : "=l"(r) : "l"(a), "l"(b), "l"(c));
    return r;
}

__device__ __forceinline__ uint32_t smem_u32(const void* p) {
    uint32_t a;
    asm("{ .reg .u64 t; cvta.to.shared.u64 t, %1; cvt.u32.u64 %0, t; }"
        : "=r"(a) : "l"(p));
    return a;
}

__global__ __launch_bounds__(NTH, 2)
void fsmn_kernel(const float* __restrict__ x,
                 const float* __restrict__ filt,
                 float* __restrict__ out)
{
    extern __shared__ uint64_t sm[];   // [2][ROWS][DPB] x | [41][DPB] filt
    uint64_t* const sx = sm;
    uint64_t* const sf = sm + 2 * XWORDS;

    const int tid = threadIdx.x;
    const int q0  = blockIdx.x * TPB;         // first tile index
    const int dpg = blockIdx.y * DPB;         // d-pair base
    const int b   = blockIdx.z;

    const uint64_t* __restrict__ xg =
        reinterpret_cast<const uint64_t*>(x) + (size_t)b * T_ * DPAL + dpg;
    uint64_t* __restrict__ og =
        reinterpret_cast<uint64_t*>(out) + (size_t)b * T_ * DPAL + dpg;
    const uint64_t* __restrict__ fg =
        reinterpret_cast<const uint64_t*>(filt) + dpg;

    // ---- stage filter slab into smem once: sf[k*DPB + dpl] = filt[k, dpg+dpl]
#pragma unroll
    for (int k = 0; k < 6; ++k) {
        const int i = tid + k * NTH;
        if (i < FWORDS)
            sf[i] = fg[(size_t)(i >> 5) * DPAL + (i & (DPB - 1))];
    }

    const uint32_t sbase = smem_u32(sx);

    // ---- cp.async tile prefetch: 3072 16B units over 224 threads ----
    auto prefetch = [&](int buf, int qt) {
        const int tb = qt * TT;
        const uint32_t db = sbase + (uint32_t)buf * XBYTES;
#pragma unroll
        for (int k = 0; k < 14; ++k) {
            const int u = tid + k * NTH;
            if (u < CHUNKS) {
                const int row = u >> 4;
                const int c16 = u & 15;
                const int t   = tb - 40 + row;
                const char* gp =
                    reinterpret_cast<const char*>(xg + (size_t)t * DPAL)
                    + c16 * 16;
                const uint32_t dst = db + (uint32_t)(row * DPB) * 8 + c16 * 16;
                const int ok = (t >= 0 && t < T_) ? 16 : 0;
                asm volatile("cp.async.cg.shared.global [%0], [%1], 16, %2;"
                             :: "r"(dst), "l"(gp), "r"(ok) : "memory");
            }
        }
        asm volatile("cp.async.commit_group;" ::: "memory");
    };

    const int dpl = tid & (DPB - 1);          // 0..31
    const int g   = tid >> 5;                 // 0..6 (16 t each)
    const uint64_t* __restrict__ sfp = sf + dpl;

    prefetch(0, q0);

    for (int i = 0; i < TPB; ++i) {
        if (i < TPB - 1) {
            prefetch((i + 1) & 1, q0 + i + 1);
            asm volatile("cp.async.wait_group 1;" ::: "memory");
        } else {
            asm volatile("cp.async.wait_group 0;" ::: "memory");
        }
        __syncthreads();

        const int tb = (q0 + i) * TT;
        const uint64_t* __restrict__ sxp = sx + (i & 1) * XWORDS + dpl;

        uint64_t acc[16];                      // [par*8 + r]
#pragma unroll
        for (int z = 0; z < 16; ++z) acc[z] = 0ull;

        // ======== A phase: left+center taps filt[0..20], both parities =====
        {
            uint64_t fL[21];
#pragma unroll
            for (int c = 0; c < 21; ++c) fL[c] = sfp[c * DPB];
#pragma unroll
            for (int par = 0; par < 2; ++par) {
                const int rb = g * 16 + par;   // smem row of x[t0-40]
                uint64_t w[RT];
#pragma unroll
                for (int u = 0; u < RT; ++u)
                    w[u] = sxp[(rb + 2 * u) * DPB];
#pragma unroll
                for (int c = 0; c < 21; ++c) {
#pragma unroll
                    for (int r = 0; r < RT; ++r)
                        acc[par * RT + r] = f2fma(fL[c], w[(c + r) & (RT - 1)],
                                                  acc[par * RT + r]);
                    if (c < 20)
                        w[c & (RT - 1)] = sxp[(rb + 2 * (c + RT)) * DPB];
                }
            }
        }

        // ======== B phase: right taps filt[21..40], both parities ==========
        {
            uint64_t fR[20];
#pragma unroll
            for (int c = 0; c < 20; ++c) fR[c] = sfp[(21 + c) * DPB];
#pragma unroll
            for (int par = 0; par < 2; ++par) {
                const int rb = g * 16 + par + 41; // smem row of x[t0+1]
                uint64_t w[RT];
#pragma unroll
                for (int u = 0; u < RT; ++u)
                    w[u] = sxp[(rb + 2 * u) * DPB];
#pragma unroll
                for (int c = 0; c < 20; ++c) {
#pragma unroll
                    for (int r = 0; r < RT; ++r)
                        acc[par * RT + r] = f2fma(fR[c], w[(c + r) & (RT - 1)],
                                                  acc[par * RT + r]);
                    if (c < 19)
                        w[c & (RT - 1)] = sxp[(rb + 2 * (c + RT)) * DPB];
                }
            }
        }

        // -------- store 16 outputs (guard: tiles 17.. reach t >= 2000) -----
#pragma unroll
        for (int par = 0; par < 2; ++par) {
            const int t0 = tb + g * 16 + par;
#pragma unroll
            for (int r = 0; r < RT; ++r) {
                const int t = t0 + 2 * r;
                if (t < T_) og[(size_t)t * DPAL + dpl] = acc[par * RT + r];
            }
        }
        __syncthreads();   // protect buf[i&1] before next prefetch
    }
}

extern "C" void kernel_launch(void* const* d_in, const int* in_sizes, int n_in,
                              void* d_out, int out_size)
{
    const float* x    = (const float*)d_in[0];   // [32, 2000, 512] f32
    const float* filt = (const float*)d_in[1];   // [41, 512] f32
    float* out        = (float*)d_out;           // [32, 2000, 512] f32

    cudaFuncSetAttribute(fsmn_kernel,
                         cudaFuncAttributeMaxDynamicSharedMemorySize,
                         SMEM_BYTES);

    dim3 grid(3,            // 3 groups x TPB=6 tiles -> 18 t-tiles
              DPAL / DPB,   // 8 d-pair slabs
              B_);          // 32 batch
    fsmn_kernel<<<grid, NTH, SMEM_BYTES>>>(x, filt, out);
}